// round 5
// baseline (speedup 1.0000x reference)
#include <cuda_runtime.h>
#include <math.h>
#include <string.h>

// GaussianBlurDM, round 4.
//
// out[b] = reflect-conv(reflect-conv(x[b], K_t, axis=H), K_t, axis=W) where
// K_t = t-fold self-convolution of the base 11-tap Gaussian (exact DCT-I
// eigenbasis identity), truncated at tail mass 5e-5.
//
// Both passes are one kernel: vertical reflect-convolution writing output
// transposed (pass1 x[h][w]->mid[w][h], pass2 mid[w][h]->out[h][w]).
// Thread = 2 adjacent columns (packed fma.rn.f32x2) x 16 output rows.
// 32-slot register ring: row refilled at step s is first consumed 17 steps
// (~540 cycles of FFMA2 issue) later -> L2 latency fully hidden in-warp.

#define BATCH 64
#define CHAN 3
#define IMG 256
#define NT 19
#define KLEN 96
#define NSLOT (NT + 1)   // slot NT = identity (safety for t<=0)

typedef unsigned long long u64;

struct BlurParams {
    float2 K[NSLOT][KLEN];  // weight duplicated into both lanes; zero-padded
    int r[NSLOT];
    int ndp[NSLOT];         // taps padded to multiple of 16
};

__device__ float g_mid[BATCH * CHAN * IMG * IMG];   // ~50 MB transposed scratch

__device__ __forceinline__ int reflect256(int v) {
    v = abs(v);
    return (v > 255) ? (510 - v) : v;
}

__device__ __forceinline__ u64 ffma2(u64 a, u64 b, u64 c) {
    u64 d;
    asm("fma.rn.f32x2 %0, %1, %2, %3;" : "=l"(d) : "l"(a), "l"(b), "l"(c));
    return d;
}

// CTA: 128 threads (one per column pair), 16 output rows. Grid: (16, C, B).
__global__ void __launch_bounds__(128, 4) conv_pass(
    const float* __restrict__ src, float* __restrict__ dst,
    const int* __restrict__ t, const __grid_constant__ BlurParams P)
{
    const int tid = threadIdx.x;
    const int m0 = blockIdx.x << 4;                    // first output row
    const int bc = blockIdx.z * CHAN + blockIdx.y;
    const u64* __restrict__ scol =
        (const u64*)(src + ((long)bc << 16)) + tid;    // row stride = 128 u64
    float* dimg = dst + ((long)bc << 16);

    const int tb = t[blockIdx.z];
    const int ti = (tb >= 1) ? ((tb > NT) ? (NT - 1) : (tb - 1)) : NT;
    const u64* __restrict__ Kw = (const u64*)P.K[ti];  // constant-bank u64
    const int r = P.r[ti];
    const int ndp = P.ndp[ti];
    const int gbase = m0 - r;

    u64 acc[16], ring[32];
    #pragma unroll
    for (int k = 0; k < 16; ++k) acc[k] = 0ull;
    #pragma unroll
    for (int m = 0; m < 32; ++m)
        ring[m] = __ldg(scol + (reflect256(gbase + m) << 7));

    #pragma unroll 1
    for (int jj = 0; jj < ndp; jj += 32) {
        // half A: taps jj..jj+15; window rows jj+u..jj+u+15 live in slots u..u+15
        #pragma unroll
        for (int u = 0; u < 16; ++u) {
            u64 w = Kw[jj + u];
            #pragma unroll
            for (int k = 0; k < 16; ++k)
                acc[k] = ffma2(ring[u + k], w, acc[k]);
            ring[u] = __ldg(scol + (reflect256(gbase + jj + 32 + u) << 7));
        }
        if (jj + 16 >= ndp) break;
        // half B: taps jj+16..jj+31; slots wrap mod 32
        #pragma unroll
        for (int u = 0; u < 16; ++u) {
            u64 w = Kw[jj + 16 + u];
            #pragma unroll
            for (int k = 0; k < 16; ++k)
                acc[k] = ffma2(ring[(16 + u + k) & 31], w, acc[k]);
            ring[16 + u] = __ldg(scol + (reflect256(gbase + jj + 48 + u) << 7));
        }
    }

    // Transposed store: column c writes dst[c][m0..m0+15] (64 B contiguous).
    const int c0 = tid << 1;
    float lo[16], hi[16];
    #pragma unroll
    for (int k = 0; k < 16; ++k) {
        float ax, ay;
        asm("mov.b64 {%0, %1}, %2;" : "=f"(ax), "=f"(ay) : "l"(acc[k]));
        lo[k] = ax; hi[k] = ay;
    }
    float4* d0 = (float4*)(dimg + c0 * IMG + m0);
    float4* d1 = (float4*)(dimg + (c0 + 1) * IMG + m0);
    #pragma unroll
    for (int q = 0; q < 4; ++q) {
        d0[q] = make_float4(lo[4 * q], lo[4 * q + 1], lo[4 * q + 2], lo[4 * q + 3]);
        d1[q] = make_float4(hi[4 * q], hi[4 * q + 1], hi[4 * q + 2], hi[4 * q + 3]);
    }
}

// ---------------------------------------------------------------------------
extern "C" void kernel_launch(void* const* d_in, const int* in_sizes, int n_in,
                              void* d_out, int out_size) {
    const float* x = (const float*)d_in[0];
    const int* t = (const int*)d_in[1];
    float* out = (float*)d_out;

    static BlurParams P;
    memset(&P, 0, sizeof(P));
    {
        // Base kernel, f32-rounded exactly like the reference's _k1d.
        double pdf[11], sum = 0.0;
        for (int i = 0; i < 11; ++i) {
            double xi = -5.0 + (double)i;
            pdf[i] = exp(-0.5 * (xi / 2.0) * (xi / 2.0));
            sum += pdf[i];
        }
        double base[11];
        for (int i = 0; i < 11; ++i)
            base[i] = (double)((float)(pdf[i] / sum));

        double f[220];
        for (int i = 0; i < 220; ++i) f[i] = 0.0;
        for (int i = 0; i < 11; ++i) f[i] = base[i];
        int hw = 5;

        const double TAIL = 5e-5;
        for (int tt = 1; tt <= NT; ++tt) {
            double acc = 0.0;
            int r = 0;
            for (int a = hw; a >= 1; --a) {
                acc += f[hw + a];
                if (2.0 * acc > TAIL) { r = a; break; }
            }
            int nd = 2 * r + 1;
            int ndp = (nd + 15) & ~15;
            if (ndp > KLEN) ndp = KLEN;
            P.r[tt - 1] = r;
            P.ndp[tt - 1] = ndp;
            for (int jj = 0; jj < nd && jj < KLEN; ++jj) {
                float w = (float)f[hw + (jj - r)];
                P.K[tt - 1][jj].x = w;
                P.K[tt - 1][jj].y = w;
            }
            if (tt < NT) {   // f = f (*) base
                int L = 2 * hw + 1;
                double g[220];
                for (int i = 0; i < 220; ++i) g[i] = 0.0;
                for (int n = 0; n < L; ++n) {
                    double fn = f[n];
                    for (int k = 0; k < 11; ++k) g[n + k] += fn * base[k];
                }
                for (int i = 0; i < 220; ++i) f[i] = g[i];
                hw += 5;
            }
        }
        // Identity slot (t <= 0 safety): single unit tap -> bit-exact copy.
        P.r[NT] = 0;
        P.ndp[NT] = 16;
        P.K[NT][0].x = 1.0f;
        P.K[NT][0].y = 1.0f;
    }

    float* mid;
    cudaGetSymbolAddress((void**)&mid, g_mid);

    dim3 block(128);
    dim3 grid(IMG / 16, CHAN, BATCH);   // 16 x 3 x 64 = 3072 CTAs
    conv_pass<<<grid, block>>>(x, mid, t, P);   // x[h][w]   -> mid[w][h]
    conv_pass<<<grid, block>>>(mid, out, t, P); // mid[w][h] -> out[h][w]
}